// round 11
// baseline (speedup 1.0000x reference)
#include <cuda_runtime.h>
#include <cstdint>

// Problem constants: B=4, H=16, S=2048, D=64.  BH = 64.
#define S_LEN 2048
#define DH    64
#define BHN   64
#define BM    128            // query rows per CTA
#define BN    64             // kv chunk width
#define NQT   (S_LEN / BM)   // 16
#define STRP  72             // packed pair-row stride (words) for Q, K, V

// Scratch: per-row inverse softmax denominators for pass 2.
__device__ float g_linv[BHN * S_LEN];

// smem words: Qp 128*72 + Kp 64*72 + Vp 64*72 = 18432 words = 73728 B
#define SM_WORDS ((BM + BN + BN) * STRP)
#define SM_BYTES (SM_WORDS * 4)

#define EXP_SCALE 0.1803368801111244f   // 0.125 * log2(e)

// ---------------------------------------------------------------------------
__device__ __forceinline__ uint32_t f2tf32(float f) {
    uint32_t r;
    asm("cvt.rna.tf32.f32 %0, %1;" : "=r"(r) : "f"(f));
    return r;
}

__device__ __forceinline__ float ex2(float x) {
    float r;
    asm("ex2.approx.f32 %0, %1;" : "=f"(r) : "f"(x));
    return r;
}

__device__ __forceinline__ void mma_tf32(float* d, const uint32_t* a,
                                         uint32_t b0, uint32_t b1) {
    asm volatile(
        "mma.sync.aligned.m16n8k8.row.col.f32.tf32.tf32.f32 "
        "{%0,%1,%2,%3}, {%4,%5,%6,%7}, {%8,%9}, {%0,%1,%2,%3};"
        : "+f"(d[0]), "+f"(d[1]), "+f"(d[2]), "+f"(d[3])
        : "r"(a[0]), "r"(a[1]), "r"(a[2]), "r"(a[3]), "r"(b0), "r"(b1));
}

// pack two float4s (cols c..c+3 and c+4..c+7) into pair-interleaved tf32 words
__device__ __forceinline__ void pack_row(uint32_t* dst, float4 f0, float4 f1) {
    uint4 w0, w1;
    w0.x = f2tf32(f0.x); w0.y = f2tf32(f1.x);
    w0.z = f2tf32(f0.y); w0.w = f2tf32(f1.y);
    w1.x = f2tf32(f0.z); w1.y = f2tf32(f1.z);
    w1.z = f2tf32(f0.w); w1.w = f2tf32(f1.w);
    *(uint4*)dst       = w0;
    *(uint4*)(dst + 4) = w1;
}

// ---------------------------------------------------------------------------
// Pass 1: S in registers end-to-end; per (bh, qt) CTA over 64-wide kv chunks.
// 8 warps; warp w owns q-rows [w*16, w*16+16).  mma m16n8k8 tf32 both GEMMs.
// Q, K stored pair-packed ({col s8+t, col s8+t+4} adjacent); V transposed and
// adjacent-kv-row packed.  All smem pre-converted to tf32.  Single-buffered;
// occupancy 2 CTAs/SM hides staging + pipe latency.
// ---------------------------------------------------------------------------
__global__ void __launch_bounds__(256, 2) attn_pass1(
    const float* __restrict__ q, const float* __restrict__ k,
    const float* __restrict__ v, float* __restrict__ out_o,
    float* __restrict__ out_p)
{
    extern __shared__ uint32_t smu[];
    uint32_t* Qp = smu;                  // [128][STRP] packed tf32 pairs
    uint32_t* Kp = Qp + BM * STRP;       // [64][STRP]  packed tf32 pairs
    uint32_t* Vp = Kp + BN * STRP;       // [64][STRP]  packed transposed tf32

    const int qt   = (NQT - 1) - (int)blockIdx.x;   // heavy tiles first
    const int bh   = (int)blockIdx.y;
    const int tid  = (int)threadIdx.x;
    const int wid  = tid >> 5;
    const int lane = tid & 31;
    const int g    = lane >> 2;           // 0..7
    const int t    = lane & 3;            // 0..3
    const int wm   = wid * 16;

    // K staging: tasks tid, tid+256 -> (row = task>>3, s = task&7)
    const int krow0 = tid >> 3,          ks0 = tid & 7;
    const int krow1 = (tid + 256) >> 3,  ks1 = tid & 7;
    // V staging: kv-row pair (2kpv, 2kpv+1), col group cgv..cgv+7
    const int kpv = tid & 31;
    const int cgv = (tid >> 5) * 8;

    // ---- prologue: stage Q packed (4 tasks/thread) ----
    const float* qg = q + ((size_t)bh * S_LEN + (size_t)qt * BM) * DH;
    #pragma unroll
    for (int i = 0; i < 4; ++i) {
        int task = tid + i * 256;
        int r = task >> 3, s = task & 7;
        float4 f0 = *(const float4*)(qg + r * DH + s * 8);
        float4 f1 = *(const float4*)(qg + r * DH + s * 8 + 4);
        pack_row(Qp + r * STRP + s * 8, f0, f1);
    }

    float acc_o[8][4];
    #pragma unroll
    for (int n = 0; n < 8; ++n)
        #pragma unroll
        for (int i = 0; i < 4; ++i) acc_o[n][i] = 0.0f;
    float rs0 = 0.0f, rs1 = 0.0f;

    float* pbase = out_p + (size_t)bh * S_LEN * S_LEN + (size_t)qt * BM * S_LEN;
    const int jmax = 2 * qt + 1;
    const int row0 = qt * BM + wm + g;
    const int row1 = row0 + 8;

    for (int j = 0; j <= jmax; ++j) {
        __syncthreads();   // previous chunk fully consumed (also orders Qp wr)

        // ---- stage K (pair-packed) and V (transposed pair-packed) ----
        {
            const float* kg = k + ((size_t)bh * S_LEN + (size_t)j * BN) * DH;
            const float* vg = v + ((size_t)bh * S_LEN + (size_t)j * BN) * DH;
            float4 a0 = *(const float4*)(kg + krow0 * DH + ks0 * 8);
            float4 a1 = *(const float4*)(kg + krow0 * DH + ks0 * 8 + 4);
            float4 b0 = *(const float4*)(kg + krow1 * DH + ks1 * 8);
            float4 b1 = *(const float4*)(kg + krow1 * DH + ks1 * 8 + 4);
            pack_row(Kp + krow0 * STRP + ks0 * 8, a0, a1);
            pack_row(Kp + krow1 * STRP + ks1 * 8, b0, b1);
            float4 e0 = *(const float4*)(vg + (size_t)(2 * kpv) * DH + cgv);
            float4 e1 = *(const float4*)(vg + (size_t)(2 * kpv) * DH + cgv + 4);
            float4 o0 = *(const float4*)(vg + (size_t)(2 * kpv + 1) * DH + cgv);
            float4 o1 = *(const float4*)(vg + (size_t)(2 * kpv + 1) * DH + cgv + 4);
            uint32_t* base = Vp + 2 * kpv;
            uint2 w;
            w.x = f2tf32(e0.x); w.y = f2tf32(o0.x); *(uint2*)(base + (cgv + 0) * STRP) = w;
            w.x = f2tf32(e0.y); w.y = f2tf32(o0.y); *(uint2*)(base + (cgv + 1) * STRP) = w;
            w.x = f2tf32(e0.z); w.y = f2tf32(o0.z); *(uint2*)(base + (cgv + 2) * STRP) = w;
            w.x = f2tf32(e0.w); w.y = f2tf32(o0.w); *(uint2*)(base + (cgv + 3) * STRP) = w;
            w.x = f2tf32(e1.x); w.y = f2tf32(o1.x); *(uint2*)(base + (cgv + 4) * STRP) = w;
            w.x = f2tf32(e1.y); w.y = f2tf32(o1.y); *(uint2*)(base + (cgv + 5) * STRP) = w;
            w.x = f2tf32(e1.z); w.y = f2tf32(o1.z); *(uint2*)(base + (cgv + 6) * STRP) = w;
            w.x = f2tf32(e1.w); w.y = f2tf32(o1.w); *(uint2*)(base + (cgv + 7) * STRP) = w;
        }
        __syncthreads();

        // ---- load Q fragments for this chunk (one LDS.64 per pair) ----
        uint32_t qf[8][4];
        #pragma unroll
        for (int s = 0; s < 8; ++s) {
            uint2 lo = *(const uint2*)(Qp + (wm + g) * STRP + s * 8 + 2 * t);
            uint2 hi = *(const uint2*)(Qp + (wm + 8 + g) * STRP + s * 8 + 2 * t);
            qf[s][0] = lo.x; qf[s][1] = hi.x; qf[s][2] = lo.y; qf[s][3] = hi.y;
        }

        // ---- S = Q K^T ----
        float accs[8][4];
        #pragma unroll
        for (int n = 0; n < 8; ++n)
            #pragma unroll
            for (int i = 0; i < 4; ++i) accs[n][i] = 0.0f;

        const uint32_t* Kb = Kp + g * STRP + 2 * t;
        #pragma unroll
        for (int n = 0; n < 8; ++n) {
            const uint32_t* kpt = Kb + n * 8 * STRP;
            #pragma unroll
            for (int s = 0; s < 8; ++s) {
                uint2 b = *(const uint2*)(kpt + s * 8);
                mma_tf32(accs[n], qf[s], b.x, b.y);
            }
        }

        // ---- exp + causal mask + P store (STG.64) + row sums; A frags ----
        const bool nomask = (j * BN + 63) <= (qt * BM + wm);
        uint32_t pa[8][4];
        float* pr0 = pbase + (size_t)(wm + g) * S_LEN + (size_t)j * BN;
        float* pr1 = pr0 + (size_t)8 * S_LEN;
        #pragma unroll
        for (int n = 0; n < 8; ++n) {
            const int c0 = j * BN + n * 8 + 2 * t;   // accumulator col 2t
            const int c1 = c0 + 1;
            float p00 = (nomask || c0 <= row0) ? ex2(accs[n][0] * EXP_SCALE) : 0.0f;
            float p01 = (nomask || c1 <= row0) ? ex2(accs[n][1] * EXP_SCALE) : 0.0f;
            float p10 = (nomask || c0 <= row1) ? ex2(accs[n][2] * EXP_SCALE) : 0.0f;
            float p11 = (nomask || c1 <= row1) ? ex2(accs[n][3] * EXP_SCALE) : 0.0f;
            rs0 += p00 + p01;
            rs1 += p10 + p11;
            *(float2*)(pr0 + n * 8 + 2 * t) = make_float2(p00, p01);
            *(float2*)(pr1 + n * 8 + 2 * t) = make_float2(p10, p11);
            // PV A-frag (slot kappa=t <- real kv row 2t; kappa=t+4 <- 2t+1)
            pa[n][0] = f2tf32(p00);
            pa[n][1] = f2tf32(p10);
            pa[n][2] = f2tf32(p01);
            pa[n][3] = f2tf32(p11);
        }

        // ---- O += P @ V ----
        const uint32_t* Vb = Vp + g * STRP + 2 * t;
        #pragma unroll
        for (int n = 0; n < 8; ++n) {
            const uint32_t* vp = Vb + n * 8 * STRP;
            #pragma unroll
            for (int s = 0; s < 8; ++s) {
                uint2 b = *(const uint2*)(vp + s * 8);
                mma_tf32(acc_o[n], pa[s], b.x, b.y);
            }
        }
    }

    // ---- row-sum reduce within quad; write 1/l; write normalized O ----
    rs0 += __shfl_xor_sync(0xffffffffu, rs0, 1);
    rs0 += __shfl_xor_sync(0xffffffffu, rs0, 2);
    rs1 += __shfl_xor_sync(0xffffffffu, rs1, 1);
    rs1 += __shfl_xor_sync(0xffffffffu, rs1, 2);
    const float inv0 = 1.0f / rs0;
    const float inv1 = 1.0f / rs1;
    if (t == 0) {
        g_linv[bh * S_LEN + qt * BM + wm + g]     = inv0;
        g_linv[bh * S_LEN + qt * BM + wm + 8 + g] = inv1;
    }

    float* og = out_o + ((size_t)bh * S_LEN + (size_t)qt * BM) * DH;
    #pragma unroll
    for (int n = 0; n < 8; ++n) {
        float2 o0 = make_float2(acc_o[n][0] * inv0, acc_o[n][1] * inv0);
        float2 o1 = make_float2(acc_o[n][2] * inv1, acc_o[n][3] * inv1);
        *(float2*)(og + (size_t)(wm + g) * DH + n * 8 + 2 * t)     = o0;
        *(float2*)(og + (size_t)(wm + 8 + g) * DH + n * 8 + 2 * t) = o1;
    }
}

// ---------------------------------------------------------------------------
// Pass 2: normalize attn_weights in place; exact zeros above the diagonal.
// (Proven at ~78% DRAM, ~245 us.)
// ---------------------------------------------------------------------------
__global__ void __launch_bounds__(256) attn_pass2(float* __restrict__ p)
{
    const unsigned idx = blockIdx.x * 256u + threadIdx.x;   // < BH*S*S/4
    const unsigned row_lin = idx >> 9;                       // bh*S + r
    const int r = (int)(row_lin & (S_LEN - 1));
    const int c = (int)(idx & 511u) * 4;

    float4* ptr = (float4*)p + idx;
    if (c > r) {
        *ptr = make_float4(0.0f, 0.0f, 0.0f, 0.0f);
    } else {
        const float inv = g_linv[row_lin];
        float4 val = *ptr;
        float4 res;
        res.x = (c + 0 <= r) ? val.x * inv : 0.0f;
        res.y = (c + 1 <= r) ? val.y * inv : 0.0f;
        res.z = (c + 2 <= r) ? val.z * inv : 0.0f;
        res.w = (c + 3 <= r) ? val.w * inv : 0.0f;
        *ptr = res;
    }
}

// Tiny no-op kernel: shifts the launch period to 4 so ncu's "-s 5 -c 1"
// lands on attn_pass1 (index 5 mod 4 == 1) instead of always pass2.
__global__ void attn_dummy() {}

// ---------------------------------------------------------------------------
extern "C" void kernel_launch(void* const* d_in, const int* in_sizes, int n_in,
                              void* d_out, int out_size)
{
    (void)in_sizes; (void)n_in; (void)out_size;
    const float* q = (const float*)d_in[0];
    const float* k = (const float*)d_in[1];
    const float* v = (const float*)d_in[2];
    // d_in[3]: causal tril mask, applied analytically.

    float* out_o = (float*)d_out;                        // [BH,S,D]
    float* out_p = out_o + (size_t)BHN * S_LEN * DH;     // [BH,S,S]

    cudaFuncSetAttribute(attn_pass1,
                         cudaFuncAttributeMaxDynamicSharedMemorySize, SM_BYTES);

    attn_dummy<<<1, 1>>>();
    attn_pass1<<<dim3(NQT, BHN), 256, SM_BYTES>>>(q, k, v, out_o, out_p);

    const unsigned total4 = (unsigned)((size_t)BHN * S_LEN * S_LEN / 4);
    attn_pass2<<<total4 / 256, 256>>>(out_p);
    attn_dummy<<<1, 1>>>();
}

// round 12
// speedup vs baseline: 1.1910x; 1.1910x over previous
#include <cuda_runtime.h>
#include <cstdint>

// Problem constants: B=4, H=16, S=2048, D=64.  BH = 64.
#define S_LEN 2048
#define DH    64
#define BHN   64
#define BM    128            // query rows per CTA
#define BN    64             // kv chunk width
#define NQT   (S_LEN / BM)   // 16
#define QSTRH 36             // Q fp16x2 words per row (32 + 4 pad)
#define STRH  40             // K/V fp16x2 words per row/col (32 + 8 pad)

// Scratch: per-row inverse softmax denominators for pass 2.
__device__ float g_linv[BHN * S_LEN];

#define KBUF (BN * STRH)         // 2560 words per K buffer
#define VBUF (BN * STRH)         // 2560 words per V buffer
// smem words: Qh 128*36 + K 2*2560 + V 2*2560 = 14848 words = 58 KB
#define SM_WORDS (BM * QSTRH + 2 * KBUF + 2 * VBUF)
#define SM_BYTES (SM_WORDS * 4)

#define EXP_SCALE 0.1803368801111244f   // 0.125 * log2(e)

// ---------------------------------------------------------------------------
__device__ __forceinline__ float ex2(float x) {
    float r;
    asm("ex2.approx.f32 %0, %1;" : "=f"(r) : "f"(x));
    return r;
}

// pack {hi, lo} floats into fp16x2 (first PTX source -> upper half)
__device__ __forceinline__ uint32_t f16pk(float hi, float lo) {
    uint32_t d;
    asm("cvt.rn.f16x2.f32 %0, %1, %2;" : "=r"(d) : "f"(hi), "f"(lo));
    return d;
}

__device__ __forceinline__ void mma_f16(float* d, const uint32_t* a,
                                        uint32_t b0, uint32_t b1) {
    asm volatile(
        "mma.sync.aligned.m16n8k16.row.col.f32.f16.f16.f32 "
        "{%0,%1,%2,%3}, {%4,%5,%6,%7}, {%8,%9}, {%0,%1,%2,%3};"
        : "+f"(d[0]), "+f"(d[1]), "+f"(d[2]), "+f"(d[3])
        : "r"(a[0]), "r"(a[1]), "r"(a[2]), "r"(a[3]), "r"(b0), "r"(b1));
}

// ---------------------------------------------------------------------------
// Pass 1: S in registers end-to-end; per (bh, qt) CTA over 64-wide kv chunks.
// 8 warps; warp w owns q-rows [w*16, w*16+16).  mma m16n8k16 FP16 (11-bit
// significand == tf32) with f32 accumulate for both GEMMs.
// Smem pair-packing: every B-fragment (b0,b1) = ONE LDS.64:
//   K row r, word pair {w_t, w_{t+4}} of each 8-word k-block stored adjacent.
//   V transposed (col-major over output dim), kv-pairs packed the same way.
// Register-staged double buffering; 1 __syncthreads per chunk.
// ---------------------------------------------------------------------------
__global__ void __launch_bounds__(256, 1) attn_pass1(
    const float* __restrict__ q, const float* __restrict__ k,
    const float* __restrict__ v, float* __restrict__ out_o,
    float* __restrict__ out_p)
{
    extern __shared__ uint32_t smu[];
    uint32_t* Qh = smu;                  // [128][QSTRH] natural fp16x2 words
    uint32_t* Ks = Qh + BM * QSTRH;      // [2][64][STRH] pair-packed fp16x2
    uint32_t* Vs = Ks + 2 * KBUF;        // [2][64][STRH] transposed pair-packed

    const int qt   = (NQT - 1) - (int)blockIdx.x;   // heavy tiles first
    const int bh   = (int)blockIdx.y;
    const int tid  = (int)threadIdx.x;
    const int wid  = tid >> 5;
    const int lane = tid & 31;
    const int g    = lane >> 2;           // 0..7
    const int t    = lane & 3;            // 0..3
    const int wm   = wid * 16;

    // K staging: 1 task/thread: row = tid>>2 (0..63), kb = tid&3 (k-block)
    const int krow = tid >> 2, kkb = tid & 3;
    // V staging: kv-row pair (2kpv, 2kpv+1), cols cgv..cgv+7
    const int kpv = tid & 31;
    const int cgv = (tid >> 5) * 8;
    const int w8  = kpv & 7;
    const int vslot = (kpv >> 3) * 8 + ((w8 < 4) ? (2 * w8) : (2 * (w8 - 4) + 1));

    // commit 16 K floats (cols kkb*16..+15 of row krow) pair-packed
    auto commitK = [&](uint32_t* kb, const float4* f) {
        const float* x = (const float*)f;   // 16 floats
        uint32_t w[8];
        #pragma unroll
        for (int i = 0; i < 8; ++i) w[i] = f16pk(x[2 * i + 1], x[2 * i]);
        uint32_t* dst = kb + krow * STRH + kkb * 8;
        #pragma unroll
        for (int i = 0; i < 4; ++i)
            *(uint2*)(dst + 2 * i) = make_uint2(w[i], w[i + 4]);
    };
    // commit V rows 2kpv,2kpv+1 x cols cgv..+7 into transposed layout
    auto commitV = [&](uint32_t* vb, float4 e0, float4 e1, float4 o0, float4 o1) {
        uint32_t* base = vb + vslot;
        base[(cgv + 0) * STRH] = f16pk(o0.x, e0.x);
        base[(cgv + 1) * STRH] = f16pk(o0.y, e0.y);
        base[(cgv + 2) * STRH] = f16pk(o0.z, e0.z);
        base[(cgv + 3) * STRH] = f16pk(o0.w, e0.w);
        base[(cgv + 4) * STRH] = f16pk(o1.x, e1.x);
        base[(cgv + 5) * STRH] = f16pk(o1.y, e1.y);
        base[(cgv + 6) * STRH] = f16pk(o1.z, e1.z);
        base[(cgv + 7) * STRH] = f16pk(o1.w, e1.w);
    };

    // ---- prologue: stage Q (natural fp16x2) + chunk 0 ----
    const float* qg = q + ((size_t)bh * S_LEN + (size_t)qt * BM) * DH;
    #pragma unroll
    for (int i = 0; i < 2; ++i) {
        int task = tid + i * 256;           // 512 tasks: r = task>>2, qtr = task&3
        int r = task >> 2, qtr = task & 3;
        const float* src = qg + r * DH + qtr * 16;
        float4 f0 = *(const float4*)(src);
        float4 f1 = *(const float4*)(src + 4);
        float4 f2 = *(const float4*)(src + 8);
        float4 f3 = *(const float4*)(src + 12);
        uint4 wa, wb;
        wa.x = f16pk(f0.y, f0.x); wa.y = f16pk(f0.w, f0.z);
        wa.z = f16pk(f1.y, f1.x); wa.w = f16pk(f1.w, f1.z);
        wb.x = f16pk(f2.y, f2.x); wb.y = f16pk(f2.w, f2.z);
        wb.z = f16pk(f3.y, f3.x); wb.w = f16pk(f3.w, f3.z);
        *(uint4*)(Qh + r * QSTRH + qtr * 8)     = wa;
        *(uint4*)(Qh + r * QSTRH + qtr * 8 + 4) = wb;
    }
    {
        const float* kg = k + (size_t)bh * S_LEN * DH;
        const float* vg = v + (size_t)bh * S_LEN * DH;
        float4 kf[4];
        #pragma unroll
        for (int i = 0; i < 4; ++i)
            kf[i] = *(const float4*)(kg + krow * DH + kkb * 16 + i * 4);
        commitK(Ks, kf);
        float4 e0 = *(const float4*)(vg + (size_t)(2 * kpv) * DH + cgv);
        float4 e1 = *(const float4*)(vg + (size_t)(2 * kpv) * DH + cgv + 4);
        float4 o0 = *(const float4*)(vg + (size_t)(2 * kpv + 1) * DH + cgv);
        float4 o1 = *(const float4*)(vg + (size_t)(2 * kpv + 1) * DH + cgv + 4);
        commitV(Vs, e0, e1, o0, o1);
    }
    __syncthreads();

    // ---- Q fragments (held for whole kernel; 16 regs) ----
    uint32_t qf[4][4];
    #pragma unroll
    for (int kb = 0; kb < 4; ++kb) {
        qf[kb][0] = Qh[(wm + g) * QSTRH + kb * 8 + t];
        qf[kb][1] = Qh[(wm + 8 + g) * QSTRH + kb * 8 + t];
        qf[kb][2] = Qh[(wm + g) * QSTRH + kb * 8 + t + 4];
        qf[kb][3] = Qh[(wm + 8 + g) * QSTRH + kb * 8 + t + 4];
    }

    float acc_o[8][4];
    #pragma unroll
    for (int n = 0; n < 8; ++n)
        #pragma unroll
        for (int i = 0; i < 4; ++i) acc_o[n][i] = 0.0f;
    float rs0 = 0.0f, rs1 = 0.0f;

    float* pbase = out_p + (size_t)bh * S_LEN * S_LEN + (size_t)qt * BM * S_LEN;
    const int jmax = 2 * qt + 1;
    const int row0 = qt * BM + wm + g;
    const int row1 = row0 + 8;

    for (int j = 0; j <= jmax; ++j) {
        const int buf = j & 1;

        // ---- issue LDGs for next chunk early (hidden behind compute) ----
        float4 kf[4], ve0, ve1, vo0, vo1;
        if (j < jmax) {
            const float* kg = k + ((size_t)bh * S_LEN + (size_t)(j + 1) * BN) * DH;
            const float* vg = v + ((size_t)bh * S_LEN + (size_t)(j + 1) * BN) * DH;
            #pragma unroll
            for (int i = 0; i < 4; ++i)
                kf[i] = *(const float4*)(kg + krow * DH + kkb * 16 + i * 4);
            ve0 = *(const float4*)(vg + (size_t)(2 * kpv) * DH + cgv);
            ve1 = *(const float4*)(vg + (size_t)(2 * kpv) * DH + cgv + 4);
            vo0 = *(const float4*)(vg + (size_t)(2 * kpv + 1) * DH + cgv);
            vo1 = *(const float4*)(vg + (size_t)(2 * kpv + 1) * DH + cgv + 4);
        }

        // ---- S = Q K^T (fp16 k16; one LDS.64 per mma) ----
        float accs[8][4];
        #pragma unroll
        for (int n = 0; n < 8; ++n)
            #pragma unroll
            for (int i = 0; i < 4; ++i) accs[n][i] = 0.0f;

        const uint32_t* Kb = Ks + buf * KBUF + g * STRH + 2 * t;
        #pragma unroll
        for (int n = 0; n < 8; ++n) {
            const uint32_t* kpt = Kb + n * 8 * STRH;
            #pragma unroll
            for (int kb = 0; kb < 4; ++kb) {
                uint2 b = *(const uint2*)(kpt + kb * 8);
                mma_f16(accs[n], qf[kb], b.x, b.y);
            }
        }

        // ---- exp + causal mask + P store (fp32 STG.64) + row sums ----
        const bool nomask = (j * BN + 63) <= (qt * BM + wm);
        uint32_t pa[4][4];
        float* pr0 = pbase + (size_t)(wm + g) * S_LEN + (size_t)j * BN;
        float* pr1 = pr0 + (size_t)8 * S_LEN;
        #pragma unroll
        for (int n = 0; n < 8; ++n) {
            const int c0 = j * BN + n * 8 + 2 * t;   // accumulator col 2t
            const int c1 = c0 + 1;
            float p00 = (nomask || c0 <= row0) ? ex2(accs[n][0] * EXP_SCALE) : 0.0f;
            float p01 = (nomask || c1 <= row0) ? ex2(accs[n][1] * EXP_SCALE) : 0.0f;
            float p10 = (nomask || c0 <= row1) ? ex2(accs[n][2] * EXP_SCALE) : 0.0f;
            float p11 = (nomask || c1 <= row1) ? ex2(accs[n][3] * EXP_SCALE) : 0.0f;
            rs0 += p00 + p01;
            rs1 += p10 + p11;
            *(float2*)(pr0 + n * 8 + 2 * t) = make_float2(p00, p01);
            *(float2*)(pr1 + n * 8 + 2 * t) = make_float2(p10, p11);
            // fp16 A-frag for PV: m = n>>1; n even -> (a0,a1), n odd -> (a2,a3)
            const int m  = n >> 1;
            const int o2 = (n & 1) << 1;
            pa[m][o2]     = f16pk(p01, p00);   // row g,   k lo/hi halves
            pa[m][o2 + 1] = f16pk(p11, p10);   // row g+8
        }

        // ---- O += P @ V (fp16 k16; one LDS.64 per mma) ----
        const uint32_t* Vb = Vs + buf * VBUF + g * STRH + 2 * t;
        #pragma unroll
        for (int n = 0; n < 8; ++n) {
            const uint32_t* vp = Vb + n * 8 * STRH;
            #pragma unroll
            for (int m = 0; m < 4; ++m) {
                uint2 b = *(const uint2*)(vp + m * 8);
                mma_f16(acc_o[n], pa[m], b.x, b.y);
            }
        }

        // ---- commit next chunk to alternate buffer ----
        if (j < jmax) {
            commitK(Ks + (buf ^ 1) * KBUF, kf);
            commitV(Vs + (buf ^ 1) * VBUF, ve0, ve1, vo0, vo1);
        }
        __syncthreads();
    }

    // ---- row-sum reduce within quad; write 1/l; write normalized O ----
    rs0 += __shfl_xor_sync(0xffffffffu, rs0, 1);
    rs0 += __shfl_xor_sync(0xffffffffu, rs0, 2);
    rs1 += __shfl_xor_sync(0xffffffffu, rs1, 1);
    rs1 += __shfl_xor_sync(0xffffffffu, rs1, 2);
    const float inv0 = 1.0f / rs0;
    const float inv1 = 1.0f / rs1;
    if (t == 0) {
        g_linv[bh * S_LEN + qt * BM + wm + g]     = inv0;
        g_linv[bh * S_LEN + qt * BM + wm + 8 + g] = inv1;
    }

    float* og = out_o + ((size_t)bh * S_LEN + (size_t)qt * BM) * DH;
    #pragma unroll
    for (int n = 0; n < 8; ++n) {
        float2 o0 = make_float2(acc_o[n][0] * inv0, acc_o[n][1] * inv0);
        float2 o1 = make_float2(acc_o[n][2] * inv1, acc_o[n][3] * inv1);
        *(float2*)(og + (size_t)(wm + g) * DH + n * 8 + 2 * t)     = o0;
        *(float2*)(og + (size_t)(wm + 8 + g) * DH + n * 8 + 2 * t) = o1;
    }
}

// ---------------------------------------------------------------------------
// Pass 2: normalize attn_weights in place; exact zeros above the diagonal.
// (Proven at ~78% DRAM, ~245 us.)
// ---------------------------------------------------------------------------
__global__ void __launch_bounds__(256) attn_pass2(float* __restrict__ p)
{
    const unsigned idx = blockIdx.x * 256u + threadIdx.x;   // < BH*S*S/4
    const unsigned row_lin = idx >> 9;                       // bh*S + r
    const int r = (int)(row_lin & (S_LEN - 1));
    const int c = (int)(idx & 511u) * 4;

    float4* ptr = (float4*)p + idx;
    if (c > r) {
        *ptr = make_float4(0.0f, 0.0f, 0.0f, 0.0f);
    } else {
        const float inv = g_linv[row_lin];
        float4 val = *ptr;
        float4 res;
        res.x = (c + 0 <= r) ? val.x * inv : 0.0f;
        res.y = (c + 1 <= r) ? val.y * inv : 0.0f;
        res.z = (c + 2 <= r) ? val.z * inv : 0.0f;
        res.w = (c + 3 <= r) ? val.w * inv : 0.0f;
        *ptr = res;
    }
}

// ---------------------------------------------------------------------------
extern "C" void kernel_launch(void* const* d_in, const int* in_sizes, int n_in,
                              void* d_out, int out_size)
{
    (void)in_sizes; (void)n_in; (void)out_size;
    const float* q = (const float*)d_in[0];
    const float* k = (const float*)d_in[1];
    const float* v = (const float*)d_in[2];
    // d_in[3]: causal tril mask, applied analytically.

    float* out_o = (float*)d_out;                        // [BH,S,D]
    float* out_p = out_o + (size_t)BHN * S_LEN * DH;     // [BH,S,S]

    cudaFuncSetAttribute(attn_pass1,
                         cudaFuncAttributeMaxDynamicSharedMemorySize, SM_BYTES);

    attn_pass1<<<dim3(NQT, BHN), 256, SM_BYTES>>>(q, k, v, out_o, out_p);

    const unsigned total4 = (unsigned)((size_t)BHN * S_LEN * S_LEN / 4);
    attn_pass2<<<total4 / 256, 256>>>(out_p);
}